// round 2
// baseline (speedup 1.0000x reference)
#include <cuda_runtime.h>

#define NFFT  4096
#define LOGN  12
#define NB    32
#define TLEN  4096
#define NF    128
#define NSERIES (NB*NF)          // 4096 series
#define NBINS 2049
#define KTOP  16
#define WIN   25
#define HALF  12
#define FFT_THREADS 512

// Scratch (static device globals; no allocation).
// g_xt: transposed input (B,F,T); reused as filtered xf by the inverse kernel.
__device__ float  g_xt[(size_t)NSERIES * TLEN];
__device__ float2 g_tw[NFFT/2];
__device__ int    g_topk_idx[NSERIES * KTOP];
__device__ float2 g_topk_val[NSERIES * KTOP];

// ---------------------------------------------------------------- twiddles
__global__ void init_tw_kernel() {
    int k = blockIdx.x * blockDim.x + threadIdx.x;
    if (k < NFFT/2) {
        double a = -2.0 * (double)k / (double)NFFT;   // units of pi
        g_tw[k] = make_float2((float)cospi(a), (float)sinpi(a));
    }
}

// ---------------------------------------------------------------- transpose (B,T,F) -> (B,F,T)
__global__ void __launch_bounds__(256) transpose_kernel(const float* __restrict__ x) {
    __shared__ float tile[32][33];
    int b  = blockIdx.z;
    int t0 = blockIdx.x * 32;
    int f0 = blockIdx.y * 32;
    int tx = threadIdx.x, ty = threadIdx.y;   // (32, 8)
    #pragma unroll
    for (int i = 0; i < 4; i++) {
        int t = t0 + ty + i*8;
        tile[ty + i*8][tx] = x[((size_t)b*TLEN + t)*NF + (f0 + tx)];
    }
    __syncthreads();
    #pragma unroll
    for (int i = 0; i < 4; i++) {
        int f = f0 + ty + i*8;
        g_xt[((size_t)(b*NF + f))*TLEN + (t0 + tx)] = tile[tx][ty + i*8];
    }
}

// ---------------------------------------------------------------- Stockham radix-2 in smem
// Forward DFT for tsign=+1 (twiddles e^{-2pi i k/N}); set tsign=-1 for unnormalized inverse.
// 12 stages (even) -> result ends in buf0.
__device__ __forceinline__ void fft_smem(float2* buf0, float2* buf1, int tid, float tsign) {
    float2* cur = buf0;
    float2* oth = buf1;
    #pragma unroll 1
    for (int s = 0; s < LOGN; s++) {
        int m = 1 << s;
        #pragma unroll
        for (int u = 0; u < (NFFT/2)/FFT_THREADS; u++) {
            int i  = tid + u*FFT_THREADS;          // butterfly id, 0..2047
            int jm = i & ~(m - 1);                 // j*m
            float2 c0 = cur[i];
            float2 c1 = cur[i + NFFT/2];
            float2 w  = g_tw[jm];
            w.y *= tsign;
            float2 su = make_float2(c0.x + c1.x, c0.y + c1.y);
            float2 df = make_float2(c0.x - c1.x, c0.y - c1.y);
            float2 wd = make_float2(w.x*df.x - w.y*df.y, w.x*df.y + w.y*df.x);
            oth[i + jm]     = su;                  // k + 2*j*m
            oth[i + jm + m] = wd;
        }
        __syncthreads();
        float2* t2 = cur; cur = oth; oth = t2;
    }
}

// ---------------------------------------------------------------- forward FFT + top-k
// One CTA per pair of series (packed real FFT: z = a + i*b).
__global__ void __launch_bounds__(FFT_THREADS) fwd_kernel() {
    extern __shared__ float2 smbuf[];
    float2* buf0 = smbuf;
    float2* buf1 = smbuf + NFFT;
    __shared__ float red_v[16];
    __shared__ int   red_i[16];

    int pair = blockIdx.x;
    int sa   = pair * 2;
    int tid  = threadIdx.x;
    const float* rowa = g_xt + (size_t)sa * TLEN;
    const float* rowb = rowa + TLEN;

    for (int t = tid; t < NFFT; t += FFT_THREADS)
        buf0[t] = make_float2(rowa[t], rowb[t]);
    __syncthreads();

    fft_smem(buf0, buf1, tid, 1.0f);   // result (Z) in buf0; buf1 free

    // magnitudes^2 of both unpacked spectra, stored in buf1's space
    float* magA = (float*)buf1;        // 2049 floats
    float* magB = magA + 2064;         // 2049 floats (padded offset)
    for (int m = tid; m < NBINS; m += FFT_THREADS) {
        float2 z  = buf0[m];
        float2 zm = buf0[(NFFT - m) & (NFFT - 1)];
        float ar = 0.5f*(z.x + zm.x), ai = 0.5f*(z.y - zm.y);   // A[m]
        float br = 0.5f*(z.y + zm.y), bi = 0.5f*(zm.x - z.x);   // B[m]
        magA[m] = ar*ar + ai*ai;
        magB[m] = br*br + bi*bi;
    }
    __syncthreads();

    // top-16 per series via 16 argmax passes (ties -> lower index, matching lax.top_k)
    for (int srs = 0; srs < 2; srs++) {
        float* mag = srs ? magB : magA;
        int sid = sa + srs;
        for (int it = 0; it < KTOP; it++) {
            float bv = -1.0f; int bi2 = NBINS;
            for (int m = tid; m < NBINS; m += FFT_THREADS) {
                float v = mag[m];
                if (v > bv) { bv = v; bi2 = m; }
            }
            #pragma unroll
            for (int off = 16; off; off >>= 1) {
                float ov = __shfl_down_sync(0xffffffffu, bv, off);
                int   oi = __shfl_down_sync(0xffffffffu, bi2, off);
                if (ov > bv || (ov == bv && oi < bi2)) { bv = ov; bi2 = oi; }
            }
            if ((tid & 31) == 0) { red_v[tid >> 5] = bv; red_i[tid >> 5] = bi2; }
            __syncthreads();
            if (tid == 0) {
                float bbv = red_v[0]; int bbi = red_i[0];
                #pragma unroll
                for (int wg = 1; wg < 16; wg++) {
                    if (red_v[wg] > bbv || (red_v[wg] == bbv && red_i[wg] < bbi)) {
                        bbv = red_v[wg]; bbi = red_i[wg];
                    }
                }
                mag[bbi] = -2.0f;                     // remove for next pass
                int m = bbi;
                float2 z  = buf0[m];
                float2 zm = buf0[(NFFT - m) & (NFFT - 1)];
                float2 val = (srs == 0)
                    ? make_float2(0.5f*(z.x + zm.x), 0.5f*(z.y - zm.y))
                    : make_float2(0.5f*(z.y + zm.y), 0.5f*(zm.x - z.x));
                g_topk_idx[sid*KTOP + it] = m;
                g_topk_val[sid*KTOP + it] = val;
            }
            __syncthreads();
        }
    }
}

// ---------------------------------------------------------------- sparse inverse FFT
// One CTA per pair; build Z = Ya + i*Yb from the 2x16 kept bins, iFFT, write xf into g_xt.
__global__ void __launch_bounds__(FFT_THREADS) inv_kernel() {
    extern __shared__ float2 smbuf[];
    float2* buf0 = smbuf;
    float2* buf1 = smbuf + NFFT;
    int pair = blockIdx.x;
    int sa   = pair * 2;
    int tid  = threadIdx.x;

    for (int t = tid; t < NFFT; t += FFT_THREADS)
        buf0[t] = make_float2(0.f, 0.f);
    __syncthreads();

    if (tid == 0) {
        // series a: Y[m] += V ; Y[N-m] += conj(V) for 0<m<N/2
        #pragma unroll 1
        for (int it = 0; it < KTOP; it++) {
            int m = g_topk_idx[sa*KTOP + it];
            float2 v = g_topk_val[sa*KTOP + it];
            buf0[m].x += v.x; buf0[m].y += v.y;
            if (m != 0 && m != NFFT/2) {
                buf0[NFFT - m].x += v.x; buf0[NFFT - m].y -= v.y;
            }
        }
        // series b: Y[m] += i*V = (-vy, vx) ; Y[N-m] += i*conj(V) = (vy, vx)
        #pragma unroll 1
        for (int it = 0; it < KTOP; it++) {
            int m = g_topk_idx[(sa+1)*KTOP + it];
            float2 v = g_topk_val[(sa+1)*KTOP + it];
            buf0[m].x += -v.y; buf0[m].y += v.x;
            if (m != 0 && m != NFFT/2) {
                buf0[NFFT - m].x += v.y; buf0[NFFT - m].y += v.x;
            }
        }
    }
    __syncthreads();

    fft_smem(buf0, buf1, tid, -1.0f);  // unnormalized inverse, result in buf0

    float* rowa = g_xt + (size_t)sa * TLEN;
    float* rowb = rowa + TLEN;
    const float scale = 1.0f / (float)NFFT;
    for (int t = tid; t < NFFT; t += FFT_THREADS) {
        float2 z = buf0[t];
        rowa[t] = z.x * scale;   // Re -> series a
        rowb[t] = z.y * scale;   // Im -> series b
    }
}

// ---------------------------------------------------------------- smoothing + transpose back
// Tile: 32 features x 128 time. Symmetric flip padding at global edges.
__global__ void __launch_bounds__(256) smooth_kernel(float* __restrict__ out) {
    __shared__ float sin_[32][153];    // 128+24 cols, row stride 153 (odd -> conflict-free)
    __shared__ float sout[128][33];
    __shared__ float swt[WIN];
    int b  = blockIdx.z;
    int f0 = blockIdx.y * 32;
    int t0 = blockIdx.x * 128;
    int tid = threadIdx.x;

    if (tid < WIN)
        swt[tid] = (0.54f - 0.46f * cospif(2.0f * (float)tid / (float)WIN)) * (1.0f / 13.5f);

    for (int idx = tid; idx < 32 * 152; idx += 256) {
        int r = idx / 152;
        int c = idx - r * 152;
        int gt = t0 + c - HALF;
        if (gt < 0)          gt = -1 - gt;          // left flip:  x[-1-i]
        else if (gt >= TLEN) gt = 2*TLEN - 1 - gt;  // right flip: x[2T-1-i]
        sin_[r][c] = g_xt[((size_t)(b*NF + f0 + r))*TLEN + gt];
    }
    __syncthreads();

    float wr[WIN];
    #pragma unroll
    for (int n = 0; n < WIN; n++) wr[n] = swt[n];

    int f  = tid & 31;
    int g  = tid >> 5;        // 0..7, each handles 16 consecutive outputs
    int c0 = g * 16;
    float v[16 + WIN - 1];
    #pragma unroll
    for (int j = 0; j < 16 + WIN - 1; j++) v[j] = sin_[f][c0 + j];
    #pragma unroll
    for (int o = 0; o < 16; o++) {
        float a = 0.f;
        #pragma unroll
        for (int n = 0; n < WIN; n++) a = fmaf(wr[n], v[o + n], a);
        sout[c0 + o][f] = a;
    }
    __syncthreads();

    for (int idx = tid; idx < 128 * 32; idx += 256) {
        int tt = idx >> 5, ff = idx & 31;
        out[((size_t)b*TLEN + (t0 + tt))*NF + (f0 + ff)] = sout[tt][ff];
    }
}

// ---------------------------------------------------------------- launch
extern "C" void kernel_launch(void* const* d_in, const int* in_sizes, int n_in,
                              void* d_out, int out_size) {
    const float* x = (const float*)d_in[0];
    float* out = (float*)d_out;
    // window_size=25, k=16 are fixed problem constants (compiled in).

    size_t fft_smem_bytes = 2 * NFFT * sizeof(float2);   // 64 KB
    cudaFuncSetAttribute(fwd_kernel, cudaFuncAttributeMaxDynamicSharedMemorySize, (int)fft_smem_bytes);
    cudaFuncSetAttribute(inv_kernel, cudaFuncAttributeMaxDynamicSharedMemorySize, (int)fft_smem_bytes);

    init_tw_kernel<<<(NFFT/2 + 255)/256, 256>>>();
    transpose_kernel<<<dim3(TLEN/32, NF/32, NB), dim3(32, 8)>>>(x);
    fwd_kernel<<<NSERIES/2, FFT_THREADS, fft_smem_bytes>>>();
    inv_kernel<<<NSERIES/2, FFT_THREADS, fft_smem_bytes>>>();
    smooth_kernel<<<dim3(TLEN/128, NF/32, NB), 256>>>(out);
}

// round 6
// speedup vs baseline: 1.2282x; 1.2282x over previous
#include <cuda_runtime.h>

#define NB    32
#define TLEN  4096
#define NF    128
#define NSERIES (NB*NF)          // 4096 series
#define NFFT  4096
#define KTOP  16
#define WIN   25
#define HALF  12
#define THR   256
#define BUFSZ 4352               // PAD(4095)=4350 -> 4351 entries, round to 4352
#define PAD(i) ((i) + ((i) >> 4))

typedef unsigned long long u64;

// Scratch (static device globals; no allocation).
__device__ float  g_xt[(size_t)NSERIES * TLEN];   // (B,F,T): input transposed, then smoothed output
__device__ float2 g_twf[NFFT];                    // e^{-2pi i k / 4096}
__device__ float2 g_H[NFFT/2 + 1];                // Hamming filter frequency response (normalized)
__device__ int    g_tidx[NSERIES * KTOP];
__device__ float2 g_tval[NSERIES * KTOP];

__device__ __forceinline__ float2 cmul(float2 a, float2 b) {
    return make_float2(fmaf(a.x, b.x, -a.y * b.y), fmaf(a.x, b.y, a.y * b.x));
}

// ---------------------------------------------------------------- init: twiddles + filter response
__global__ void init_kernel() {
    int k = blockIdx.x * blockDim.x + threadIdx.x;
    if (k < NFFT) {
        double a = -(double)k / 2048.0;   // pi-units of -2k/4096
        g_twf[k] = make_float2((float)cospi(a), (float)sinpi(a));
    }
    if (k <= NFFT/2) {
        // H[k] = sum_n w[n] e^{+2pi i k (n-12)/4096},  w normalized by 13.5
        float hr = 0.f, hi = 0.f;
        #pragma unroll 1
        for (int n = 0; n < WIN; n++) {
            float w = (0.54f - 0.46f * cospif(2.0f * (float)n / 25.0f)) * (1.0f / 13.5f);
            float s, c;
            sincospif((float)k * (float)(n - HALF) / 2048.0f, &s, &c);
            hr = fmaf(w, c, hr);
            hi = fmaf(w, s, hi);
        }
        g_H[k] = make_float2(hr, hi);
    }
}

// ---------------------------------------------------------------- transpose (B,T,F) -> (B,F,T)
__global__ void __launch_bounds__(256) transpose_in_kernel(const float* __restrict__ x) {
    __shared__ float tile[32][33];
    int b  = blockIdx.z;
    int t0 = blockIdx.x * 32;
    int f0 = blockIdx.y * 32;
    int tx = threadIdx.x, ty = threadIdx.y;   // (32, 8)
    #pragma unroll
    for (int i = 0; i < 4; i++) {
        int t = t0 + ty + i*8;
        tile[ty + i*8][tx] = x[((size_t)b*TLEN + t)*NF + (f0 + tx)];
    }
    __syncthreads();
    #pragma unroll
    for (int i = 0; i < 4; i++) {
        int f = f0 + ty + i*8;
        g_xt[((size_t)(b*NF + f))*TLEN + (t0 + tx)] = tile[tx][ty + i*8];
    }
}

// ---------------------------------------------------------------- transpose (B,F,T) -> (B,T,F)
__global__ void __launch_bounds__(256) transpose_out_kernel(float* __restrict__ out) {
    __shared__ float tile[32][33];
    int b  = blockIdx.z;
    int t0 = blockIdx.x * 32;
    int f0 = blockIdx.y * 32;
    int tx = threadIdx.x, ty = threadIdx.y;   // (32, 8)
    #pragma unroll
    for (int i = 0; i < 4; i++) {
        int f = f0 + ty + i*8;
        tile[ty + i*8][tx] = g_xt[((size_t)(b*NF + f))*TLEN + (t0 + tx)];
    }
    __syncthreads();
    #pragma unroll
    for (int i = 0; i < 4; i++) {
        int t = t0 + ty + i*8;
        out[((size_t)b*TLEN + t)*NF + (f0 + tx)] = tile[tx][ty + i*8];
    }
}

// ---------------------------------------------------------------- radix-4 Stockham, 6 stages
// FWD=true: e^{-2pi i}. FWD=false: e^{+2pi i} (unnormalized inverse). Result ends in b0.
template<bool FWD>
__device__ __forceinline__ void fft4(float2* b0, float2* b1, int tid) {
    float2* cur = b0;
    float2* oth = b1;
    #pragma unroll
    for (int st = 0; st < 6; st++) {
        const int s = 1 << (2*st);
        #pragma unroll
        for (int u = 0; u < 4; u++) {
            int i  = tid + u * THR;                // butterfly id 0..1023
            int jm = i & ~(s - 1);
            float2 a = cur[PAD(i)];
            float2 b = cur[PAD(i + 1024)];
            float2 c = cur[PAD(i + 2048)];
            float2 d = cur[PAD(i + 3072)];
            float2 apc = make_float2(a.x + c.x, a.y + c.y);
            float2 amc = make_float2(a.x - c.x, a.y - c.y);
            float2 bpd = make_float2(b.x + d.x, b.y + d.y);
            float2 bmd = make_float2(b.x - d.x, b.y - d.y);
            float2 y0 = make_float2(apc.x + bpd.x, apc.y + bpd.y);
            float2 t2 = make_float2(apc.x - bpd.x, apc.y - bpd.y);
            float2 t1, t3;
            if (FWD) {   // u1 = amc - i*bmd, u3 = amc + i*bmd
                t1 = make_float2(amc.x + bmd.y, amc.y - bmd.x);
                t3 = make_float2(amc.x - bmd.y, amc.y + bmd.x);
            } else {
                t1 = make_float2(amc.x - bmd.y, amc.y + bmd.x);
                t3 = make_float2(amc.x + bmd.y, amc.y - bmd.x);
            }
            float2 y1, y2, y3;
            if (st < 5) {
                float2 w1 = g_twf[jm];
                if (!FWD) w1.y = -w1.y;
                float2 w2 = make_float2(fmaf(w1.x, w1.x, -w1.y * w1.y), 2.f * w1.x * w1.y);
                float2 w3 = cmul(w1, w2);
                y1 = cmul(w1, t1);
                y2 = cmul(w2, t2);
                y3 = cmul(w3, t3);
            } else {     // last stage: i < 1024 == s, so jm == 0, twiddles are 1
                y1 = t1; y2 = t2; y3 = t3;
            }
            int off = i + 3 * jm;
            oth[PAD(off)]       = y0;
            oth[PAD(off + s)]   = y1;
            oth[PAD(off + 2*s)] = y2;
            oth[PAD(off + 3*s)] = y3;
        }
        __syncthreads();
        float2* tmp = cur; cur = oth; oth = tmp;
    }
}

// ---------------------------------------------------------------- forward FFT + register top-k
// One CTA per series pair (packed real FFT: z = a + i*b).
__global__ void __launch_bounds__(THR) fwd_kernel() {
    extern __shared__ float2 sm[];
    float2* b0 = sm;
    float2* b1 = sm + BUFSZ;
    __shared__ u64 sKA[2][8], sKB[2][8];

    int tid = threadIdx.x;
    int sa  = blockIdx.x * 2;
    const float* rowa = g_xt + (size_t)sa * TLEN;
    const float* rowb = rowa + TLEN;

    #pragma unroll
    for (int u = 0; u < 16; u++) {
        int t = tid + u * THR;
        b0[PAD(t)] = make_float2(rowa[t], rowb[t]);
    }
    __syncthreads();

    fft4<true>(b0, b1, tid);   // spectrum Z in b0

    // Pack magnitude keys in registers. Thread owns bins 8*tid..8*tid+7; tid0 also owns 2048.
    // key = mag_bits << 12 | (4095 - m): higher mag wins; ties -> smaller m (lax.top_k order).
    u64 keyA[8], keyB[8];
    u64 keyA8 = 0, keyB8 = 0;
    const int mb = tid * 8;
    #pragma unroll
    for (int k = 0; k < 8; k++) {
        int m = mb + k;
        float2 z  = b0[PAD(m)];
        float2 zm = b0[PAD((NFFT - m) & (NFFT - 1))];
        float ar = z.x + zm.x, ai = z.y - zm.y;     // 2*A[m]
        float br = z.y + zm.y, bi = zm.x - z.x;     // 2*B[m]
        float magA = fmaf(ar, ar, ai * ai);
        float magB = fmaf(br, br, bi * bi);
        keyA[k] = ((u64)__float_as_uint(magA) << 12) | (unsigned)(4095 - m);
        keyB[k] = ((u64)__float_as_uint(magB) << 12) | (unsigned)(4095 - m);
    }
    if (tid == 0) {
        float2 z = b0[PAD(2048)];
        float magA = 4.f * z.x * z.x;
        float magB = 4.f * z.y * z.y;
        keyA8 = ((u64)__float_as_uint(magA) << 12) | (unsigned)(4095 - 2048);
        keyB8 = ((u64)__float_as_uint(magB) << 12) | (unsigned)(4095 - 2048);
    }

    int wid = tid >> 5, lane = tid & 31;
    for (int it = 0; it < KTOP; it++) {
        u64 bA = keyA8, bB = keyB8;
        #pragma unroll
        for (int k = 0; k < 8; k++) {
            if (keyA[k] > bA) bA = keyA[k];
            if (keyB[k] > bB) bB = keyB[k];
        }
        #pragma unroll
        for (int off = 16; off; off >>= 1) {
            u64 oA = __shfl_down_sync(0xffffffffu, bA, off);
            u64 oB = __shfl_down_sync(0xffffffffu, bB, off);
            if (oA > bA) bA = oA;
            if (oB > bB) bB = oB;
        }
        int p = it & 1;
        if (lane == 0) { sKA[p][wid] = bA; sKB[p][wid] = bB; }
        __syncthreads();
        u64 wA = sKA[p][0], wB = sKB[p][0];
        #pragma unroll
        for (int w = 1; w < 8; w++) {
            if (sKA[p][w] > wA) wA = sKA[p][w];
            if (sKB[p][w] > wB) wB = sKB[p][w];
        }
        // winners claim (keys are unique; consumed keys become 0 < any live key)
        #pragma unroll
        for (int k = 0; k < 8; k++) {
            if (keyA[k] == wA) {
                int m = mb + k;
                float2 z  = b0[PAD(m)];
                float2 zm = b0[PAD((NFFT - m) & (NFFT - 1))];
                g_tidx[sa*KTOP + it] = m;
                g_tval[sa*KTOP + it] = make_float2(0.5f*(z.x + zm.x), 0.5f*(z.y - zm.y));
                keyA[k] = 0;
            }
            if (keyB[k] == wB) {
                int m = mb + k;
                float2 z  = b0[PAD(m)];
                float2 zm = b0[PAD((NFFT - m) & (NFFT - 1))];
                g_tidx[(sa+1)*KTOP + it] = m;
                g_tval[(sa+1)*KTOP + it] = make_float2(0.5f*(z.y + zm.y), 0.5f*(zm.x - z.x));
                keyB[k] = 0;
            }
        }
        if (keyA8 != 0 && keyA8 == wA) {
            float2 z = b0[PAD(2048)];
            g_tidx[sa*KTOP + it] = 2048;
            g_tval[sa*KTOP + it] = make_float2(z.x, 0.f);
            keyA8 = 0;
        }
        if (keyB8 != 0 && keyB8 == wB) {
            float2 z = b0[PAD(2048)];
            g_tidx[(sa+1)*KTOP + it] = 2048;
            g_tval[(sa+1)*KTOP + it] = make_float2(z.y, 0.f);
            keyB8 = 0;
        }
    }
}

// ---------------------------------------------------------------- inverse: sparse filtered spectrum
// Builds Z = (Va*H) + i*(Vb*H), inverse FFTs -> smoothed interior directly; the 24 edge
// samples per series (flip-pad != circular) are recomputed exactly from the raw bins.
__global__ void __launch_bounds__(THR) inv_kernel() {
    extern __shared__ float2 sm[];
    float2* b0 = sm;
    float2* b1 = sm + BUFSZ;
    __shared__ float sraw[2][48];   // [series][0..23]=xf[0..23], [24..47]=xf[T-24..T-1]
    __shared__ float swt[WIN];

    int tid = threadIdx.x;
    int sa  = blockIdx.x * 2;

    #pragma unroll
    for (int u = 0; u < 16; u++)
        b0[PAD(tid + u*THR)] = make_float2(0.f, 0.f);

    if (tid < WIN)
        swt[tid] = (0.54f - 0.46f * cospif(2.0f * (float)tid / 25.0f)) * (1.0f / 13.5f);

    // raw (unfiltered) xf at the 48 edge positions per series, from the 16 kept bins
    if (tid < 96) {
        int srs = tid & 1, pos = tid >> 1;            // pos 0..47
        int t = pos < 24 ? pos : TLEN - 48 + pos;
        const int*    idx = g_tidx + (size_t)(sa + srs) * KTOP;
        const float2* val = g_tval + (size_t)(sa + srs) * KTOP;
        float acc = 0.f;
        #pragma unroll
        for (int j = 0; j < KTOP; j++) {
            int m = idx[j];
            float2 v = val[j];
            float2 tw = g_twf[(m * t) & (NFFT - 1)];  // e^{-2pi i mt/N}; e^{+} = conj
            float coef = (m == 0 || m == 2048) ? 1.f : 2.f;
            // 2*Re(V * e^{+2pi i mt/N}) = 2*(Vr*tw.x + Vi*tw.y)
            acc = fmaf(coef * v.x, tw.x, acc);
            acc = fmaf(coef * v.y, tw.y, acc);
        }
        sraw[srs][pos] = acc * (1.0f / (float)NFFT);
    }
    __syncthreads();

    // scatter series a: Z[m] = V*H[m]; Z[N-m] = conj(V*H[m])
    if (tid < KTOP) {
        int m = g_tidx[sa*KTOP + tid];
        float2 vf = cmul(g_tval[sa*KTOP + tid], g_H[m]);
        b0[PAD(m)] = vf;
        if (m > 0 && m < 2048) b0[PAD(NFFT - m)] = make_float2(vf.x, -vf.y);
    }
    __syncthreads();
    // scatter series b (additive): Z[m] += i*W*H[m]; Z[N-m] += i*conj(W*H[m])
    if (tid < KTOP) {
        int m = g_tidx[(sa+1)*KTOP + tid];
        float2 wf = cmul(g_tval[(sa+1)*KTOP + tid], g_H[m]);
        float2 c = b0[PAD(m)];
        c.x -= wf.y; c.y += wf.x;
        b0[PAD(m)] = c;
        if (m > 0 && m < 2048) {
            float2 c2 = b0[PAD(NFFT - m)];
            c2.x += wf.y; c2.y += wf.x;
            b0[PAD(NFFT - m)] = c2;
        }
    }
    __syncthreads();

    fft4<false>(b0, b1, tid);     // unnormalized inverse; Re -> smoothed a, Im -> smoothed b

    float* rowa = g_xt + (size_t)sa * TLEN;
    float* rowb = rowa + TLEN;
    const float sc = 1.0f / (float)NFFT;
    #pragma unroll
    for (int u = 0; u < 16; u++) {
        int t = tid + u * THR;
        if (t >= HALF && t < TLEN - HALF) {
            float2 z = b0[PAD(t)];
            rowa[t] = z.x * sc;
            rowb[t] = z.y * sc;
        }
    }

    // exact edge outputs via flip-padded direct convolution of raw values
    if (tid < 48) {
        int srs = tid & 1, j = tid >> 1;              // j 0..23
        float* row = srs ? rowb : rowa;
        float acc = 0.f;
        if (j < 12) {                                  // left edge, t = j
            #pragma unroll
            for (int n = 0; n < WIN; n++) {
                int q = j + n - HALF;
                q = q < 0 ? -1 - q : q;                // flip, lands in [0,23]
                acc = fmaf(swt[n], sraw[srs][q], acc);
            }
            row[j] = acc;
        } else {                                       // right edge, t = T-12+(j-12)
            int e = j - 12;
            #pragma unroll
            for (int n = 0; n < WIN; n++) {
                int q = e + n;                         // 0..35
                int loc = q < 24 ? q : 47 - q;         // flip, lands in [0,23]
                acc = fmaf(swt[n], sraw[srs][24 + loc], acc);
            }
            row[TLEN - 12 + e] = acc;
        }
    }
}

// ---------------------------------------------------------------- launch
extern "C" void kernel_launch(void* const* d_in, const int* in_sizes, int n_in,
                              void* d_out, int out_size) {
    const float* x = (const float*)d_in[0];
    float* out = (float*)d_out;

    size_t smem = 2 * BUFSZ * sizeof(float2);   // 69632 B
    cudaFuncSetAttribute(fwd_kernel, cudaFuncAttributeMaxDynamicSharedMemorySize, (int)smem);
    cudaFuncSetAttribute(inv_kernel, cudaFuncAttributeMaxDynamicSharedMemorySize, (int)smem);

    init_kernel<<<16, 256>>>();
    transpose_in_kernel<<<dim3(TLEN/32, NF/32, NB), dim3(32, 8)>>>(x);
    fwd_kernel<<<NSERIES/2, THR, smem>>>();
    inv_kernel<<<NSERIES/2, THR, smem>>>();
    transpose_out_kernel<<<dim3(TLEN/32, NF/32, NB), dim3(32, 8)>>>(out);
}

// round 8
// speedup vs baseline: 1.2623x; 1.0278x over previous
#include <cuda_runtime.h>

#define NB    32
#define TLEN  4096
#define NF    128
#define NFFT  4096
#define KTOP  16
#define WIN   25
#define HALF  12
#define THR   256
#define BUFSZ 4352               // PAD(4095)=4350 -> need 4351, round to 4352
#define PAD(i) ((i) + ((i) >> 4))

typedef unsigned long long u64;

__device__ float2 g_twf[NFFT];                    // e^{-2pi i k / 4096}
__device__ float2 g_H[NFFT/2 + 1];                // Hamming filter frequency response (normalized)

__device__ __forceinline__ float2 cmul(float2 a, float2 b) {
    return make_float2(fmaf(a.x, b.x, -a.y * b.y), fmaf(a.x, b.y, a.y * b.x));
}

// ---------------------------------------------------------------- init: twiddles + filter response
__global__ void init_kernel() {
    int k = blockIdx.x * blockDim.x + threadIdx.x;
    if (k < NFFT) {
        double a = -(double)k / 2048.0;   // pi-units of -2k/4096
        g_twf[k] = make_float2((float)cospi(a), (float)sinpi(a));
    }
    if (k <= NFFT/2) {
        // H[k] = sum_n w[n] e^{+2pi i k (n-12)/4096},  w normalized by 13.5
        float hr = 0.f, hi = 0.f;
        #pragma unroll 1
        for (int n = 0; n < WIN; n++) {
            float w = (0.54f - 0.46f * cospif(2.0f * (float)n / 25.0f)) * (1.0f / 13.5f);
            float s, c;
            sincospif((float)k * (float)(n - HALF) / 2048.0f, &s, &c);
            hr = fmaf(w, c, hr);
            hi = fmaf(w, s, hi);
        }
        g_H[k] = make_float2(hr, hi);
    }
}

// ---------------------------------------------------------------- 4-pt DFT, in place (y[q]=sum_p x[p] w4^{pq})
template<bool FWD>
__device__ __forceinline__ void dft4(float2& x0, float2& x1, float2& x2, float2& x3) {
    float2 apc = make_float2(x0.x + x2.x, x0.y + x2.y);
    float2 amc = make_float2(x0.x - x2.x, x0.y - x2.y);
    float2 bpd = make_float2(x1.x + x3.x, x1.y + x3.y);
    float2 bmd = make_float2(x1.x - x3.x, x1.y - x3.y);
    x0 = make_float2(apc.x + bpd.x, apc.y + bpd.y);
    x2 = make_float2(apc.x - bpd.x, apc.y - bpd.y);
    if (FWD) {   // y1 = amc - i*bmd ; y3 = amc + i*bmd
        x1 = make_float2(amc.x + bmd.y, amc.y - bmd.x);
        x3 = make_float2(amc.x - bmd.y, amc.y + bmd.x);
    } else {
        x1 = make_float2(amc.x - bmd.y, amc.y + bmd.x);
        x3 = make_float2(amc.x + bmd.y, amc.y - bmd.x);
    }
}

// multiply by constant twiddle (cr, ci) given for FORWARD; inverse conjugates
template<bool FWD>
__device__ __forceinline__ float2 twc(float2 a, float cr, float ci) {
    float s = FWD ? ci : -ci;
    return make_float2(fmaf(a.x, cr, -a.y * s), fmaf(a.x, s, a.y * cr));
}

#define C16 0.9238795325112867f
#define S16 0.3826834323650898f
#define RQ2 0.7071067811865476f

// 16-pt DFT in registers; output X[q] ends up at a[((q&3)<<2)|(q>>2)]
template<bool FWD>
__device__ __forceinline__ void dft16(float2* a) {
    dft4<FWD>(a[0], a[4], a[8],  a[12]);
    dft4<FWD>(a[1], a[5], a[9],  a[13]);
    dft4<FWD>(a[2], a[6], a[10], a[14]);
    dft4<FWD>(a[3], a[7], a[11], a[15]);
    // twiddle a[p1+4k2] *= w16^{p1*k2}
    a[5]  = twc<FWD>(a[5],   C16, -S16);
    a[9]  = twc<FWD>(a[9],   RQ2, -RQ2);
    a[13] = twc<FWD>(a[13],  S16, -C16);
    a[6]  = twc<FWD>(a[6],   RQ2, -RQ2);
    a[10] = twc<FWD>(a[10],  0.f, -1.f);
    a[14] = twc<FWD>(a[14], -RQ2, -RQ2);
    a[7]  = twc<FWD>(a[7],   S16, -C16);
    a[11] = twc<FWD>(a[11], -RQ2, -RQ2);
    a[15] = twc<FWD>(a[15], -C16,  S16);
    dft4<FWD>(a[0],  a[1],  a[2],  a[3]);
    dft4<FWD>(a[4],  a[5],  a[6],  a[7]);
    dft4<FWD>(a[8],  a[9],  a[10], a[11]);
    dft4<FWD>(a[12], a[13], a[14], a[15]);
}

// ---------------------------------------------------------------- radix-16 Stockham, 3 stages, single buffer
// FWD: e^{-2pi i}; else unnormalized inverse. 256 threads, 1 butterfly each per stage.
template<bool FWD>
__device__ __forceinline__ void fft16_3(float2* buf, int tid) {
    #pragma unroll
    for (int st = 0; st < 3; st++) {
        const int s = 1 << (4 * st);          // 1, 16, 256
        const int i = tid;
        const int jm = i & ~(s - 1);
        float2 a[16];
        #pragma unroll
        for (int p = 0; p < 16; p++) a[p] = buf[PAD(i + 256 * p)];
        __syncthreads();
        dft16<FWD>(a);
        const int off = i + 15 * jm;
        if (st < 2) {
            float2 w1 = g_twf[jm];
            if (!FWD) w1.y = -w1.y;
            float2 wq = w1;
            buf[PAD(off)] = a[0];             // q=0: twiddle 1; X[0] at a[0]
            #pragma unroll
            for (int q = 1; q < 16; q++) {
                float2 y = a[((q & 3) << 2) | (q >> 2)];
                buf[PAD(off + q * s)] = cmul(wq, y);
                wq = cmul(wq, w1);
            }
        } else {                              // jm==0, no twiddles
            #pragma unroll
            for (int q = 0; q < 16; q++)
                buf[PAD(off + q * s)] = a[((q & 3) << 2) | (q >> 2)];
        }
        __syncthreads();
    }
}

// ---------------------------------------------------------------- fused: load -> FFT -> topk -> filter -> iFFT -> store
__global__ void __launch_bounds__(THR) spectral_kernel(const float* __restrict__ x,
                                                       float* __restrict__ out) {
    extern __shared__ float2 buf[];           // BUFSZ float2
    __shared__ u64    sKA[2][8], sKB[2][8];
    __shared__ int    sIdx[2][KTOP];
    __shared__ float2 sVal[2][KTOP];
    __shared__ float  sraw[2][48];            // raw xf at t in [0,24) and [T-24,T)
    __shared__ float  swt[WIN];

    const int tid = threadIdx.x;
    const int P = blockIdx.x;                 // pair id: b = P>>6, features f=2p, 2p+1
    const int b = P >> 6;
    const int f = (P & 63) * 2;
    const float* xin  = x   + (size_t)b * TLEN * NF + f;
    float*       obase = out + (size_t)b * TLEN * NF + f;

    // load packed pair: (a_t, b_t) = x[b][t][f..f+1], one float2 per t
    #pragma unroll
    for (int u = 0; u < 16; u++) {
        int t = tid + u * THR;
        buf[PAD(t)] = *(const float2*)(xin + (size_t)t * NF);
    }
    if (tid < WIN)
        swt[tid] = (0.54f - 0.46f * cospif(2.0f * (float)tid / 25.0f)) * (1.0f / 13.5f);
    __syncthreads();

    fft16_3<true>(buf, tid);                  // spectrum Z in buf

    // ---- register top-k over bins 0..2048 for both unpacked spectra
    // key = mag_bits << 12 | (4095 - m): higher mag wins; ties -> smaller m (lax.top_k order)
    u64 keyA[8], keyB[8];
    u64 keyA8 = 0, keyB8 = 0;
    const int mb = tid * 8;
    #pragma unroll
    for (int k = 0; k < 8; k++) {
        int m = mb + k;
        float2 z  = buf[PAD(m)];
        float2 zm = buf[PAD((NFFT - m) & (NFFT - 1))];
        float ar = z.x + zm.x, ai = z.y - zm.y;     // 2*A[m]
        float br = z.y + zm.y, bi = zm.x - z.x;     // 2*B[m]
        float magA = fmaf(ar, ar, ai * ai);
        float magB = fmaf(br, br, bi * bi);
        keyA[k] = ((u64)__float_as_uint(magA) << 12) | (unsigned)(4095 - m);
        keyB[k] = ((u64)__float_as_uint(magB) << 12) | (unsigned)(4095 - m);
    }
    if (tid == 0) {
        float2 z = buf[PAD(2048)];
        keyA8 = ((u64)__float_as_uint(4.f * z.x * z.x) << 12) | (unsigned)(4095 - 2048);
        keyB8 = ((u64)__float_as_uint(4.f * z.y * z.y) << 12) | (unsigned)(4095 - 2048);
    }

    const int wid = tid >> 5, lane = tid & 31;
    for (int it = 0; it < KTOP; it++) {
        u64 bA = keyA8, bB = keyB8;
        #pragma unroll
        for (int k = 0; k < 8; k++) {
            if (keyA[k] > bA) bA = keyA[k];
            if (keyB[k] > bB) bB = keyB[k];
        }
        #pragma unroll
        for (int off = 16; off; off >>= 1) {
            u64 oA = __shfl_down_sync(0xffffffffu, bA, off);
            u64 oB = __shfl_down_sync(0xffffffffu, bB, off);
            if (oA > bA) bA = oA;
            if (oB > bB) bB = oB;
        }
        int pp = it & 1;
        if (lane == 0) { sKA[pp][wid] = bA; sKB[pp][wid] = bB; }
        __syncthreads();
        u64 wA = sKA[pp][0], wB = sKB[pp][0];
        #pragma unroll
        for (int w = 1; w < 8; w++) {
            if (sKA[pp][w] > wA) wA = sKA[pp][w];
            if (sKB[pp][w] > wB) wB = sKB[pp][w];
        }
        // winners claim (keys unique; consumed keys -> 0)
        #pragma unroll
        for (int k = 0; k < 8; k++) {
            if (keyA[k] == wA) {
                int m = mb + k;
                float2 z  = buf[PAD(m)];
                float2 zm = buf[PAD((NFFT - m) & (NFFT - 1))];
                sIdx[0][it] = m;
                sVal[0][it] = make_float2(0.5f*(z.x + zm.x), 0.5f*(z.y - zm.y));
                keyA[k] = 0;
            }
            if (keyB[k] == wB) {
                int m = mb + k;
                float2 z  = buf[PAD(m)];
                float2 zm = buf[PAD((NFFT - m) & (NFFT - 1))];
                sIdx[1][it] = m;
                sVal[1][it] = make_float2(0.5f*(z.y + zm.y), 0.5f*(zm.x - z.x));
                keyB[k] = 0;
            }
        }
        if (keyA8 != 0 && keyA8 == wA) {
            float2 z = buf[PAD(2048)];
            sIdx[0][it] = 2048; sVal[0][it] = make_float2(z.x, 0.f);
            keyA8 = 0;
        }
        if (keyB8 != 0 && keyB8 == wB) {
            float2 z = buf[PAD(2048)];
            sIdx[1][it] = 2048; sVal[1][it] = make_float2(z.y, 0.f);
            keyB8 = 0;
        }
    }
    __syncthreads();   // sIdx/sVal complete; buf (spectrum) no longer needed

    // zero buffer; meanwhile low threads compute raw edge values from the kept bins
    #pragma unroll
    for (int u = 0; u < 16; u++)
        buf[PAD(tid + u * THR)] = make_float2(0.f, 0.f);
    if (tid < 96) {
        int srs = tid & 1, pos = tid >> 1;            // pos 0..47
        int t = pos < 24 ? pos : TLEN - 48 + pos;
        float acc = 0.f;
        #pragma unroll
        for (int j = 0; j < KTOP; j++) {
            int m = sIdx[srs][j];
            float2 v = sVal[srs][j];
            float2 tw = g_twf[(m * t) & (NFFT - 1)];  // conj = e^{+2pi i mt/N}
            float coef = (m == 0 || m == 2048) ? 1.f : 2.f;
            acc = fmaf(coef * v.x, tw.x, acc);        // 2*Re(V e^{+i...}) = 2(Vr*c + Vi*s)
            acc = fmaf(coef * v.y, tw.y, acc);
        }
        sraw[srs][pos] = acc * (1.0f / (float)NFFT);
    }
    __syncthreads();

    // scatter filtered bins: series a
    if (tid < KTOP) {
        int m = sIdx[0][tid];
        float2 vf = cmul(sVal[0][tid], g_H[m]);
        buf[PAD(m)] = vf;
        if (m > 0 && m < 2048) buf[PAD(NFFT - m)] = make_float2(vf.x, -vf.y);
    }
    __syncthreads();
    // series b (additive, times i)
    if (tid < KTOP) {
        int m = sIdx[1][tid];
        float2 wf = cmul(sVal[1][tid], g_H[m]);
        float2 c = buf[PAD(m)];
        c.x -= wf.y; c.y += wf.x;
        buf[PAD(m)] = c;
        if (m > 0 && m < 2048) {
            float2 c2 = buf[PAD(NFFT - m)];
            c2.x += wf.y; c2.y += wf.x;
            buf[PAD(NFFT - m)] = c2;
        }
    }
    __syncthreads();

    fft16_3<false>(buf, tid);   // unnormalized inverse; Re -> smoothed a, Im -> smoothed b

    // interior store: out[b][t][f..f+1] as one float2
    const float sc = 1.0f / (float)NFFT;
    #pragma unroll
    for (int u = 0; u < 16; u++) {
        int t = tid + u * THR;
        if (t >= HALF && t < TLEN - HALF) {
            float2 z = buf[PAD(t)];
            *(float2*)(obase + (size_t)t * NF) = make_float2(z.x * sc, z.y * sc);
        }
    }

    // exact edge outputs via flip-padded direct convolution of raw values
    if (tid < 48) {
        int srs = tid & 1, j = tid >> 1;              // j 0..23
        float acc = 0.f;
        if (j < 12) {                                  // left edge, t = j
            #pragma unroll
            for (int n = 0; n < WIN; n++) {
                int q = j + n - HALF;
                q = q < 0 ? -1 - q : q;                // flip, lands in [0,23]
                acc = fmaf(swt[n], sraw[srs][q], acc);
            }
            obase[(size_t)j * NF + srs] = acc;
        } else {                                       // right edge, t = T-12+e
            int e = j - 12;
            #pragma unroll
            for (int n = 0; n < WIN; n++) {
                int q = e + n;                         // 0..35
                int loc = q < 24 ? q : 47 - q;         // flip, lands in [0,23]
                acc = fmaf(swt[n], sraw[srs][24 + loc], acc);
            }
            obase[(size_t)(TLEN - 12 + e) * NF + srs] = acc;
        }
    }
}

// ---------------------------------------------------------------- launch
extern "C" void kernel_launch(void* const* d_in, const int* in_sizes, int n_in,
                              void* d_out, int out_size) {
    const float* x = (const float*)d_in[0];
    float* out = (float*)d_out;

    size_t smem = BUFSZ * sizeof(float2);   // 34816 B (< 48KB default limit)
    init_kernel<<<16, 256>>>();
    spectral_kernel<<<NB * NF / 2, THR, smem>>>(x, out);
}

// round 9
// speedup vs baseline: 1.5280x; 1.2105x over previous
#include <cuda_runtime.h>

#define NB    32
#define TLEN  4096
#define NF    128
#define NFFT  4096
#define KTOP  16
#define WIN   25
#define HALF  12
#define THR   256
#define BUFSZ 4352               // PAD(4095)=4350 -> need 4351, round to 4352
#define PAD(i) ((i) + ((i) >> 4))

typedef unsigned long long u64;

__device__ float2 g_twf[NFFT];                    // e^{-2pi i k / 4096}
__device__ float2 g_H[NFFT/2 + 1];                // Hamming filter freq response (normalized)

__device__ __forceinline__ float2 cmul(float2 a, float2 b) {
    return make_float2(fmaf(a.x, b.x, -a.y * b.y), fmaf(a.x, b.y, a.y * b.x));
}

// ---------------------------------------------------------------- init: twiddles + filter response
__global__ void init_kernel() {
    int k = blockIdx.x * blockDim.x + threadIdx.x;
    if (k < NFFT) {
        double a = -(double)k / 2048.0;   // pi-units of -2k/4096
        g_twf[k] = make_float2((float)cospi(a), (float)sinpi(a));
    }
    if (k <= NFFT/2) {
        float hr = 0.f, hi = 0.f;
        #pragma unroll 1
        for (int n = 0; n < WIN; n++) {
            float w = (0.54f - 0.46f * cospif(2.0f * (float)n / 25.0f)) * (1.0f / 13.5f);
            float s, c;
            sincospif((float)k * (float)(n - HALF) / 2048.0f, &s, &c);
            hr = fmaf(w, c, hr);
            hi = fmaf(w, s, hi);
        }
        g_H[k] = make_float2(hr, hi);
    }
}

// ---------------------------------------------------------------- 4-pt DFT in place
template<bool FWD>
__device__ __forceinline__ void dft4(float2& x0, float2& x1, float2& x2, float2& x3) {
    float2 apc = make_float2(x0.x + x2.x, x0.y + x2.y);
    float2 amc = make_float2(x0.x - x2.x, x0.y - x2.y);
    float2 bpd = make_float2(x1.x + x3.x, x1.y + x3.y);
    float2 bmd = make_float2(x1.x - x3.x, x1.y - x3.y);
    x0 = make_float2(apc.x + bpd.x, apc.y + bpd.y);
    x2 = make_float2(apc.x - bpd.x, apc.y - bpd.y);
    if (FWD) {
        x1 = make_float2(amc.x + bmd.y, amc.y - bmd.x);
        x3 = make_float2(amc.x - bmd.y, amc.y + bmd.x);
    } else {
        x1 = make_float2(amc.x - bmd.y, amc.y + bmd.x);
        x3 = make_float2(amc.x + bmd.y, amc.y - bmd.x);
    }
}

template<bool FWD>
__device__ __forceinline__ float2 twc(float2 a, float cr, float ci) {
    float s = FWD ? ci : -ci;
    return make_float2(fmaf(a.x, cr, -a.y * s), fmaf(a.x, s, a.y * cr));
}

#define C16 0.9238795325112867f
#define S16 0.3826834323650898f
#define RQ2 0.7071067811865476f

// 16-pt DFT in registers; X[q] ends at a[((q&3)<<2)|(q>>2)]
template<bool FWD>
__device__ __forceinline__ void dft16(float2* a) {
    dft4<FWD>(a[0], a[4], a[8],  a[12]);
    dft4<FWD>(a[1], a[5], a[9],  a[13]);
    dft4<FWD>(a[2], a[6], a[10], a[14]);
    dft4<FWD>(a[3], a[7], a[11], a[15]);
    a[5]  = twc<FWD>(a[5],   C16, -S16);
    a[9]  = twc<FWD>(a[9],   RQ2, -RQ2);
    a[13] = twc<FWD>(a[13],  S16, -C16);
    a[6]  = twc<FWD>(a[6],   RQ2, -RQ2);
    a[10] = twc<FWD>(a[10],  0.f, -1.f);
    a[14] = twc<FWD>(a[14], -RQ2, -RQ2);
    a[7]  = twc<FWD>(a[7],   S16, -C16);
    a[11] = twc<FWD>(a[11], -RQ2, -RQ2);
    a[15] = twc<FWD>(a[15], -C16,  S16);
    dft4<FWD>(a[0],  a[1],  a[2],  a[3]);
    dft4<FWD>(a[4],  a[5],  a[6],  a[7]);
    dft4<FWD>(a[8],  a[9],  a[10], a[11]);
    dft4<FWD>(a[12], a[13], a[14], a[15]);
}

// ---------------------------------------------------------------- radix-16 Stockham, 3 stages, single buffer
// Twiddles from a squaring tree (depth 4) instead of a 15-deep serial chain.
template<bool FWD>
__device__ __forceinline__ void fft16_3(float2* buf, int tid) {
    #pragma unroll
    for (int st = 0; st < 3; st++) {
        const int s = 1 << (4 * st);          // 1, 16, 256
        const int i = tid;
        const int jm = i & ~(s - 1);
        float2 a[16];
        #pragma unroll
        for (int p = 0; p < 16; p++) a[p] = buf[PAD(i + 256 * p)];
        __syncthreads();
        dft16<FWD>(a);
        const int off = i + 15 * jm;
        if (st < 2) {
            float2 w1 = g_twf[jm];
            if (!FWD) w1.y = -w1.y;
            float2 w2 = cmul(w1, w1);
            float2 w3 = cmul(w2, w1);
            float2 w4 = cmul(w2, w2);
            float2 w5 = cmul(w4, w1);
            float2 w6 = cmul(w4, w2);
            float2 w7 = cmul(w4, w3);
            float2 w8 = cmul(w4, w4);
            buf[PAD(off)]        = a[0];
            buf[PAD(off + s)]    = cmul(w1, a[4]);
            buf[PAD(off + 2*s)]  = cmul(w2, a[8]);
            buf[PAD(off + 3*s)]  = cmul(w3, a[12]);
            buf[PAD(off + 4*s)]  = cmul(w4, a[1]);
            buf[PAD(off + 5*s)]  = cmul(w5, a[5]);
            buf[PAD(off + 6*s)]  = cmul(w6, a[9]);
            buf[PAD(off + 7*s)]  = cmul(w7, a[13]);
            buf[PAD(off + 8*s)]  = cmul(w8, a[2]);
            buf[PAD(off + 9*s)]  = cmul(cmul(w8, w1), a[6]);
            buf[PAD(off + 10*s)] = cmul(cmul(w8, w2), a[10]);
            buf[PAD(off + 11*s)] = cmul(cmul(w8, w3), a[14]);
            buf[PAD(off + 12*s)] = cmul(cmul(w8, w4), a[3]);
            buf[PAD(off + 13*s)] = cmul(cmul(w8, w5), a[7]);
            buf[PAD(off + 14*s)] = cmul(cmul(w8, w6), a[11]);
            buf[PAD(off + 15*s)] = cmul(cmul(w8, w7), a[15]);
        } else {                              // jm == 0, no twiddles
            #pragma unroll
            for (int q = 0; q < 16; q++)
                buf[PAD(off + q * s)] = a[((q & 3) << 2) | (q >> 2)];
        }
        __syncthreads();
    }
}

// ---------------------------------------------------------------- fused kernel
__global__ void __launch_bounds__(THR, 3) spectral_kernel(const float* __restrict__ x,
                                                          float* __restrict__ out) {
    extern __shared__ float2 buf[];                 // BUFSZ float2 + 2*2048 u64 sorted keys
    u64* sSA = (u64*)(buf + BUFSZ);                 // [k*256 + tid], k=0..7 (column-major)
    u64* sSB = sSA + 2048;
    __shared__ u64    sWinA[KTOP], sWinB[KTOP];
    __shared__ int    sIdx[2][KTOP];
    __shared__ float2 sVal[2][KTOP];
    __shared__ float  sraw[2][48];
    __shared__ float  swt[WIN];

    const int tid = threadIdx.x;
    const int P = blockIdx.x;
    const int b = P >> 6;
    const int f = (P & 63) * 2;
    const float* xin   = x   + (size_t)b * TLEN * NF + f;
    float*       obase = out + (size_t)b * TLEN * NF + f;

    #pragma unroll
    for (int u = 0; u < 16; u++) {
        int t = tid + u * THR;
        buf[PAD(t)] = *(const float2*)(xin + (size_t)t * NF);
    }
    if (tid < KTOP) { sWinA[tid] = 0; sWinB[tid] = 0; }
    if (tid < WIN)
        swt[tid] = (0.54f - 0.46f * cospif(2.0f * (float)tid / 25.0f)) * (1.0f / 13.5f);
    __syncthreads();

    fft16_3<true>(buf, tid);                        // spectrum Z in buf

    // ---- keys: mag_bits<<12 | (4095-m). Unique; order == lax.top_k (ties -> lower m).
    u64 kA[8], kB[8];
    u64 keyA8 = 0, keyB8 = 0;
    const int mb = tid * 8;
    #pragma unroll
    for (int k = 0; k < 8; k++) {
        int m = mb + k;
        float2 z  = buf[PAD(m)];
        float2 zm = buf[PAD((NFFT - m) & (NFFT - 1))];
        float ar = z.x + zm.x, ai = z.y - zm.y;
        float br = z.y + zm.y, bi = zm.x - z.x;
        float magA = fmaf(ar, ar, ai * ai);
        float magB = fmaf(br, br, bi * bi);
        kA[k] = ((u64)__float_as_uint(magA) << 12) | (unsigned)(4095 - m);
        kB[k] = ((u64)__float_as_uint(magB) << 12) | (unsigned)(4095 - m);
    }
    if (tid == 0) {
        float2 z = buf[PAD(2048)];
        keyA8 = ((u64)__float_as_uint(4.f * z.x * z.x) << 12) | (unsigned)(4095 - 2048);
        keyB8 = ((u64)__float_as_uint(4.f * z.y * z.y) << 12) | (unsigned)(4095 - 2048);
    }

    // ---- per-thread descending sort (19-comparator network), spill to private smem column
    #define CSW(i, j) do { \
        if (kA[i] < kA[j]) { u64 _t = kA[i]; kA[i] = kA[j]; kA[j] = _t; } \
        if (kB[i] < kB[j]) { u64 _t = kB[i]; kB[i] = kB[j]; kB[j] = _t; } \
    } while (0)
    CSW(0,1); CSW(2,3); CSW(4,5); CSW(6,7);
    CSW(0,2); CSW(1,3); CSW(4,6); CSW(5,7);
    CSW(1,2); CSW(5,6);
    CSW(0,4); CSW(1,5); CSW(2,6); CSW(3,7);
    CSW(2,4); CSW(3,5);
    CSW(1,2); CSW(3,4); CSW(5,6);
    #undef CSW
    #pragma unroll
    for (int k = 0; k < 8; k++) { sSA[k * THR + tid] = kA[k]; sSB[k * THR + tid] = kB[k]; }

    u64 candA = kA[0], candB = kB[0];
    int pA = 1, pB = 1;
    const int lane = tid & 31;

    for (int it = 0; it < KTOP; it++) {
        u64 bA = candA, bB = candB;
        if (tid == 0) { if (keyA8 > bA) bA = keyA8; if (keyB8 > bB) bB = keyB8; }
        #pragma unroll
        for (int off = 16; off; off >>= 1) {
            u64 oA = __shfl_down_sync(0xffffffffu, bA, off);
            u64 oB = __shfl_down_sync(0xffffffffu, bB, off);
            if (oA > bA) bA = oA;
            if (oB > bB) bB = oB;
        }
        if (lane == 0) { atomicMax(&sWinA[it], bA); atomicMax(&sWinB[it], bB); }
        __syncthreads();
        u64 wA = sWinA[it], wB = sWinB[it];
        if (candA == wA) {
            int m = 4095 - (int)(wA & 0xFFFu);
            float2 z  = buf[PAD(m)];
            float2 zm = buf[PAD((NFFT - m) & (NFFT - 1))];
            sIdx[0][it] = m;
            sVal[0][it] = make_float2(0.5f*(z.x + zm.x), 0.5f*(z.y - zm.y));
            candA = (pA < 8) ? sSA[pA * THR + tid] : 0;
            pA++;
        }
        if (candB == wB) {
            int m = 4095 - (int)(wB & 0xFFFu);
            float2 z  = buf[PAD(m)];
            float2 zm = buf[PAD((NFFT - m) & (NFFT - 1))];
            sIdx[1][it] = m;
            sVal[1][it] = make_float2(0.5f*(z.y + zm.y), 0.5f*(zm.x - z.x));
            candB = (pB < 8) ? sSB[pB * THR + tid] : 0;
            pB++;
        }
        if (tid == 0) {
            if (keyA8 != 0 && keyA8 == wA) {
                float2 z = buf[PAD(2048)];
                sIdx[0][it] = 2048; sVal[0][it] = make_float2(z.x, 0.f);
                keyA8 = 0;
            }
            if (keyB8 != 0 && keyB8 == wB) {
                float2 z = buf[PAD(2048)];
                sIdx[1][it] = 2048; sVal[1][it] = make_float2(z.y, 0.f);
                keyB8 = 0;
            }
        }
    }
    __syncthreads();   // sIdx/sVal complete; spectrum no longer needed

    // zero buffer; low threads compute raw edge values from the kept bins
    #pragma unroll
    for (int u = 0; u < 16; u++)
        buf[PAD(tid + u * THR)] = make_float2(0.f, 0.f);
    if (tid < 96) {
        int srs = tid & 1, pos = tid >> 1;            // pos 0..47
        int t = pos < 24 ? pos : TLEN - 48 + pos;
        float acc = 0.f;
        #pragma unroll
        for (int j = 0; j < KTOP; j++) {
            int m = sIdx[srs][j];
            float2 v = sVal[srs][j];
            float2 tw = g_twf[(m * t) & (NFFT - 1)];  // conj = e^{+2pi i mt/N}
            float coef = (m == 0 || m == 2048) ? 1.f : 2.f;
            acc = fmaf(coef * v.x, tw.x, acc);
            acc = fmaf(coef * v.y, tw.y, acc);
        }
        sraw[srs][pos] = acc * (1.0f / (float)NFFT);
    }
    __syncthreads();

    // scatter filtered bins: series a
    if (tid < KTOP) {
        int m = sIdx[0][tid];
        float2 vf = cmul(sVal[0][tid], g_H[m]);
        buf[PAD(m)] = vf;
        if (m > 0 && m < 2048) buf[PAD(NFFT - m)] = make_float2(vf.x, -vf.y);
    }
    __syncthreads();
    // series b (additive, times i)
    if (tid < KTOP) {
        int m = sIdx[1][tid];
        float2 wf = cmul(sVal[1][tid], g_H[m]);
        float2 c = buf[PAD(m)];
        c.x -= wf.y; c.y += wf.x;
        buf[PAD(m)] = c;
        if (m > 0 && m < 2048) {
            float2 c2 = buf[PAD(NFFT - m)];
            c2.x += wf.y; c2.y += wf.x;
            buf[PAD(NFFT - m)] = c2;
        }
    }
    __syncthreads();

    fft16_3<false>(buf, tid);   // unnormalized inverse; Re -> smoothed a, Im -> smoothed b

    const float sc = 1.0f / (float)NFFT;
    #pragma unroll
    for (int u = 0; u < 16; u++) {
        int t = tid + u * THR;
        if (t >= HALF && t < TLEN - HALF) {
            float2 z = buf[PAD(t)];
            *(float2*)(obase + (size_t)t * NF) = make_float2(z.x * sc, z.y * sc);
        }
    }

    // exact edge outputs via flip-padded direct convolution of raw values
    if (tid < 48) {
        int srs = tid & 1, j = tid >> 1;              // j 0..23
        float acc = 0.f;
        if (j < 12) {                                  // left edge, t = j
            #pragma unroll
            for (int n = 0; n < WIN; n++) {
                int q = j + n - HALF;
                q = q < 0 ? -1 - q : q;
                acc = fmaf(swt[n], sraw[srs][q], acc);
            }
            obase[(size_t)j * NF + srs] = acc;
        } else {                                       // right edge, t = T-12+e
            int e = j - 12;
            #pragma unroll
            for (int n = 0; n < WIN; n++) {
                int q = e + n;
                int loc = q < 24 ? q : 47 - q;
                acc = fmaf(swt[n], sraw[srs][24 + loc], acc);
            }
            obase[(size_t)(TLEN - 12 + e) * NF + srs] = acc;
        }
    }
}

// ---------------------------------------------------------------- launch
extern "C" void kernel_launch(void* const* d_in, const int* in_sizes, int n_in,
                              void* d_out, int out_size) {
    const float* x = (const float*)d_in[0];
    float* out = (float*)d_out;

    size_t smem = BUFSZ * sizeof(float2) + 2 * 2048 * sizeof(u64);   // 34816 + 32768 = 67584
    cudaFuncSetAttribute(spectral_kernel, cudaFuncAttributeMaxDynamicSharedMemorySize, (int)smem);

    init_kernel<<<16, 256>>>();
    spectral_kernel<<<NB * NF / 2, THR, smem>>>(x, out);
}

// round 10
// speedup vs baseline: 1.8382x; 1.2030x over previous
#include <cuda_runtime.h>

#define NB    32
#define TLEN  4096
#define NF    128
#define NFFT  4096
#define KTOP  16
#define WIN   25
#define HALF  12
#define THR   256
#define BUFSZ 4352               // PAD(4095)=4350 -> need 4351, round to 4352
#define PAD(i) ((i) + ((i) >> 4))

typedef unsigned long long u64;

__device__ float2 g_twf[NFFT];                    // e^{-2pi i k / 4096}
__device__ float2 g_H[NFFT/2 + 1];                // Hamming filter freq response (normalized)

__device__ __forceinline__ float2 cmul(float2 a, float2 b) {
    return make_float2(fmaf(a.x, b.x, -a.y * b.y), fmaf(a.x, b.y, a.y * b.x));
}

// ---------------------------------------------------------------- init: twiddles + filter response
__global__ void init_kernel() {
    int k = blockIdx.x * blockDim.x + threadIdx.x;
    if (k < NFFT) {
        double a = -(double)k / 2048.0;   // pi-units of -2k/4096
        g_twf[k] = make_float2((float)cospi(a), (float)sinpi(a));
    }
    if (k <= NFFT/2) {
        float hr = 0.f, hi = 0.f;
        #pragma unroll 1
        for (int n = 0; n < WIN; n++) {
            float w = (0.54f - 0.46f * cospif(2.0f * (float)n / 25.0f)) * (1.0f / 13.5f);
            float s, c;
            sincospif((float)k * (float)(n - HALF) / 2048.0f, &s, &c);
            hr = fmaf(w, c, hr);
            hi = fmaf(w, s, hi);
        }
        g_H[k] = make_float2(hr, hi);
    }
}

// ---------------------------------------------------------------- 4-pt DFT in place
template<bool FWD>
__device__ __forceinline__ void dft4(float2& x0, float2& x1, float2& x2, float2& x3) {
    float2 apc = make_float2(x0.x + x2.x, x0.y + x2.y);
    float2 amc = make_float2(x0.x - x2.x, x0.y - x2.y);
    float2 bpd = make_float2(x1.x + x3.x, x1.y + x3.y);
    float2 bmd = make_float2(x1.x - x3.x, x1.y - x3.y);
    x0 = make_float2(apc.x + bpd.x, apc.y + bpd.y);
    x2 = make_float2(apc.x - bpd.x, apc.y - bpd.y);
    if (FWD) {
        x1 = make_float2(amc.x + bmd.y, amc.y - bmd.x);
        x3 = make_float2(amc.x - bmd.y, amc.y + bmd.x);
    } else {
        x1 = make_float2(amc.x - bmd.y, amc.y + bmd.x);
        x3 = make_float2(amc.x + bmd.y, amc.y - bmd.x);
    }
}

template<bool FWD>
__device__ __forceinline__ float2 twc(float2 a, float cr, float ci) {
    float s = FWD ? ci : -ci;
    return make_float2(fmaf(a.x, cr, -a.y * s), fmaf(a.x, s, a.y * cr));
}

#define C16 0.9238795325112867f
#define S16 0.3826834323650898f
#define RQ2 0.7071067811865476f

// 16-pt DFT in registers; X[q] ends at a[((q&3)<<2)|(q>>2)]
template<bool FWD>
__device__ __forceinline__ void dft16(float2* a) {
    dft4<FWD>(a[0], a[4], a[8],  a[12]);
    dft4<FWD>(a[1], a[5], a[9],  a[13]);
    dft4<FWD>(a[2], a[6], a[10], a[14]);
    dft4<FWD>(a[3], a[7], a[11], a[15]);
    a[5]  = twc<FWD>(a[5],   C16, -S16);
    a[9]  = twc<FWD>(a[9],   RQ2, -RQ2);
    a[13] = twc<FWD>(a[13],  S16, -C16);
    a[6]  = twc<FWD>(a[6],   RQ2, -RQ2);
    a[10] = twc<FWD>(a[10],  0.f, -1.f);
    a[14] = twc<FWD>(a[14], -RQ2, -RQ2);
    a[7]  = twc<FWD>(a[7],   S16, -C16);
    a[11] = twc<FWD>(a[11], -RQ2, -RQ2);
    a[15] = twc<FWD>(a[15], -C16,  S16);
    dft4<FWD>(a[0],  a[1],  a[2],  a[3]);
    dft4<FWD>(a[4],  a[5],  a[6],  a[7]);
    dft4<FWD>(a[8],  a[9],  a[10], a[11]);
    dft4<FWD>(a[12], a[13], a[14], a[15]);
}

// ---------------------------------------------------------------- radix-16 Stockham, 3 stages, single buffer
template<bool FWD>
__device__ __forceinline__ void fft16_3(float2* buf, int tid) {
    #pragma unroll
    for (int st = 0; st < 3; st++) {
        const int s = 1 << (4 * st);          // 1, 16, 256
        const int i = tid;
        const int jm = i & ~(s - 1);
        float2 a[16];
        #pragma unroll
        for (int p = 0; p < 16; p++) a[p] = buf[PAD(i + 256 * p)];
        __syncthreads();
        dft16<FWD>(a);
        const int off = i + 15 * jm;
        if (st < 2) {
            float2 w1 = g_twf[jm];
            if (!FWD) w1.y = -w1.y;
            float2 w2 = cmul(w1, w1);
            float2 w3 = cmul(w2, w1);
            float2 w4 = cmul(w2, w2);
            float2 w5 = cmul(w4, w1);
            float2 w6 = cmul(w4, w2);
            float2 w7 = cmul(w4, w3);
            float2 w8 = cmul(w4, w4);
            buf[PAD(off)]        = a[0];
            buf[PAD(off + s)]    = cmul(w1, a[4]);
            buf[PAD(off + 2*s)]  = cmul(w2, a[8]);
            buf[PAD(off + 3*s)]  = cmul(w3, a[12]);
            buf[PAD(off + 4*s)]  = cmul(w4, a[1]);
            buf[PAD(off + 5*s)]  = cmul(w5, a[5]);
            buf[PAD(off + 6*s)]  = cmul(w6, a[9]);
            buf[PAD(off + 7*s)]  = cmul(w7, a[13]);
            buf[PAD(off + 8*s)]  = cmul(w8, a[2]);
            buf[PAD(off + 9*s)]  = cmul(cmul(w8, w1), a[6]);
            buf[PAD(off + 10*s)] = cmul(cmul(w8, w2), a[10]);
            buf[PAD(off + 11*s)] = cmul(cmul(w8, w3), a[14]);
            buf[PAD(off + 12*s)] = cmul(cmul(w8, w4), a[3]);
            buf[PAD(off + 13*s)] = cmul(cmul(w8, w5), a[7]);
            buf[PAD(off + 14*s)] = cmul(cmul(w8, w6), a[11]);
            buf[PAD(off + 15*s)] = cmul(cmul(w8, w7), a[15]);
        } else {                              // jm == 0, no twiddles
            #pragma unroll
            for (int q = 0; q < 16; q++)
                buf[PAD(off + q * s)] = a[((q & 3) << 2) | (q >> 2)];
        }
        __syncthreads();
    }
}

// select k[p] from 8 registers (p in 1..7; else 0), branch-free
__device__ __forceinline__ u64 sel8(const u64* k, int p) {
    u64 r = 0;
    r = (p == 1) ? k[1] : r;
    r = (p == 2) ? k[2] : r;
    r = (p == 3) ? k[3] : r;
    r = (p == 4) ? k[4] : r;
    r = (p == 5) ? k[5] : r;
    r = (p == 6) ? k[6] : r;
    r = (p == 7) ? k[7] : r;
    return r;
}

__device__ __forceinline__ u64 warp_max_u64(u64 v) {
    #pragma unroll
    for (int off = 16; off; off >>= 1) {
        u64 o = __shfl_xor_sync(0xffffffffu, v, off);
        if (o > v) v = o;
    }
    return v;
}

// ---------------------------------------------------------------- fused kernel
__global__ void __launch_bounds__(THR, 4) spectral_kernel(const float* __restrict__ x,
                                                          float* __restrict__ out) {
    extern __shared__ float2 buf[];                 // BUFSZ float2
    __shared__ u64    warpTop[2][8][KTOP];          // per-warp sorted top-16, per series
    __shared__ int    sIdx[2][KTOP];
    __shared__ float2 sVal[2][KTOP];
    __shared__ float  sraw[2][48];
    __shared__ float  swt[WIN];

    const int tid  = threadIdx.x;
    const int wid  = tid >> 5;
    const int lane = tid & 31;
    const int P = blockIdx.x;
    const int b = P >> 6;
    const int f = (P & 63) * 2;
    const float* xin   = x   + (size_t)b * TLEN * NF + f;
    float*       obase = out + (size_t)b * TLEN * NF + f;

    #pragma unroll
    for (int u = 0; u < 16; u++) {
        int t = tid + u * THR;
        buf[PAD(t)] = *(const float2*)(xin + (size_t)t * NF);
    }
    if (tid < WIN)
        swt[tid] = (0.54f - 0.46f * cospif(2.0f * (float)tid / 25.0f)) * (1.0f / 13.5f);
    __syncthreads();

    fft16_3<true>(buf, tid);                        // spectrum Z in buf

    // ---- keys over bins 0..2047 at stride 256 (conflict-free smem loads)
    // key = mag_bits<<12 | (4095-m): unique; order == lax.top_k (ties -> lower m)
    u64 kA[8], kB[8];
    #pragma unroll
    for (int k = 0; k < 8; k++) {
        int m = tid + k * THR;                      // 0..2047
        float2 z  = buf[PAD(m)];
        float2 zm = buf[PAD((NFFT - m) & (NFFT - 1))];
        float ar = z.x + zm.x, ai = z.y - zm.y;     // 2*A[m]
        float br = z.y + zm.y, bi = zm.x - z.x;     // 2*B[m]
        float magA = fmaf(ar, ar, ai * ai);
        float magB = fmaf(br, br, bi * bi);
        kA[k] = ((u64)__float_as_uint(magA) << 12) | (unsigned)(4095 - m);
        kB[k] = ((u64)__float_as_uint(magB) << 12) | (unsigned)(4095 - m);
    }

    // ---- per-thread descending sort (19-comparator network)
    #define CSW(i, j) do { \
        if (kA[i] < kA[j]) { u64 _t = kA[i]; kA[i] = kA[j]; kA[j] = _t; } \
        if (kB[i] < kB[j]) { u64 _t = kB[i]; kB[i] = kB[j]; kB[j] = _t; } \
    } while (0)
    CSW(0,1); CSW(2,3); CSW(4,5); CSW(6,7);
    CSW(0,2); CSW(1,3); CSW(4,6); CSW(5,7);
    CSW(1,2); CSW(5,6);
    CSW(0,4); CSW(1,5); CSW(2,6); CSW(3,7);
    CSW(2,4); CSW(3,5);
    CSW(1,2); CSW(3,4); CSW(5,6);
    #undef CSW

    // ---- warp-local top-16 (no barriers): heads advance via register select
    {
        u64 cA = kA[0], cB = kB[0];
        int pA = 1, pB = 1;
        #pragma unroll 1
        for (int it = 0; it < KTOP; it++) {
            u64 wA = warp_max_u64(cA);
            u64 wB = warp_max_u64(cB);
            if (cA == wA) {
                warpTop[0][wid][it] = wA;
                cA = sel8(kA, pA); pA++;
            }
            if (cB == wB) {
                warpTop[1][wid][it] = wB;
                cB = sel8(kB, pB); pB++;
            }
        }
    }
    __syncthreads();

    // ---- CTA merge: warp 0 -> series A, warp 1 -> series B. Lanes 0..7 hold warp-list
    // heads, lane 8 holds the bin-2048 singleton. 16 shfl-max rounds, winner extracts.
    if (wid < 2) {
        const int s = wid;
        u64 cand = 0;
        int p = 1;
        if (lane < 8) cand = warpTop[s][lane][0];
        else if (lane == 8) {
            float2 z = buf[PAD(2048)];
            float mag = (s == 0) ? 4.f * z.x * z.x : 4.f * z.y * z.y;
            cand = ((u64)__float_as_uint(mag) << 12) | (unsigned)(4095 - 2048);
        }
        #pragma unroll 1
        for (int it = 0; it < KTOP; it++) {
            u64 win = warp_max_u64(cand);
            if (cand == win) {
                int m = 4095 - (int)(win & 0xFFFu);
                float2 z  = buf[PAD(m)];
                float2 zm = buf[PAD((NFFT - m) & (NFFT - 1))];
                sIdx[s][it] = m;
                sVal[s][it] = (s == 0)
                    ? make_float2(0.5f * (z.x + zm.x), 0.5f * (z.y - zm.y))
                    : make_float2(0.5f * (z.y + zm.y), 0.5f * (zm.x - z.x));
                if (lane < 8) { cand = (p < KTOP) ? warpTop[s][lane][p] : 0; p++; }
                else cand = 0;
            }
        }
    }
    __syncthreads();   // sIdx/sVal complete; spectrum no longer needed

    // zero buffer; low threads compute raw edge values from the kept bins
    #pragma unroll
    for (int u = 0; u < 16; u++)
        buf[PAD(tid + u * THR)] = make_float2(0.f, 0.f);
    if (tid < 96) {
        int srs = tid & 1, pos = tid >> 1;            // pos 0..47
        int t = pos < 24 ? pos : TLEN - 48 + pos;
        float acc = 0.f;
        #pragma unroll
        for (int j = 0; j < KTOP; j++) {
            int m = sIdx[srs][j];
            float2 v = sVal[srs][j];
            float2 tw = g_twf[(m * t) & (NFFT - 1)];  // conj = e^{+2pi i mt/N}
            float coef = (m == 0 || m == 2048) ? 1.f : 2.f;
            acc = fmaf(coef * v.x, tw.x, acc);
            acc = fmaf(coef * v.y, tw.y, acc);
        }
        sraw[srs][pos] = acc * (1.0f / (float)NFFT);
    }
    __syncthreads();

    // scatter filtered bins: series a
    if (tid < KTOP) {
        int m = sIdx[0][tid];
        float2 vf = cmul(sVal[0][tid], g_H[m]);
        buf[PAD(m)] = vf;
        if (m > 0 && m < 2048) buf[PAD(NFFT - m)] = make_float2(vf.x, -vf.y);
    }
    __syncthreads();
    // series b (additive, times i)
    if (tid < KTOP) {
        int m = sIdx[1][tid];
        float2 wf = cmul(sVal[1][tid], g_H[m]);
        float2 c = buf[PAD(m)];
        c.x -= wf.y; c.y += wf.x;
        buf[PAD(m)] = c;
        if (m > 0 && m < 2048) {
            float2 c2 = buf[PAD(NFFT - m)];
            c2.x += wf.y; c2.y += wf.x;
            buf[PAD(NFFT - m)] = c2;
        }
    }
    __syncthreads();

    fft16_3<false>(buf, tid);   // unnormalized inverse; Re -> smoothed a, Im -> smoothed b

    const float sc = 1.0f / (float)NFFT;
    #pragma unroll
    for (int u = 0; u < 16; u++) {
        int t = tid + u * THR;
        if (t >= HALF && t < TLEN - HALF) {
            float2 z = buf[PAD(t)];
            *(float2*)(obase + (size_t)t * NF) = make_float2(z.x * sc, z.y * sc);
        }
    }

    // exact edge outputs via flip-padded direct convolution of raw values
    if (tid < 48) {
        int srs = tid & 1, j = tid >> 1;              // j 0..23
        float acc = 0.f;
        if (j < 12) {                                  // left edge, t = j
            #pragma unroll
            for (int n = 0; n < WIN; n++) {
                int q = j + n - HALF;
                q = q < 0 ? -1 - q : q;
                acc = fmaf(swt[n], sraw[srs][q], acc);
            }
            obase[(size_t)j * NF + srs] = acc;
        } else {                                       // right edge, t = T-12+e
            int e = j - 12;
            #pragma unroll
            for (int n = 0; n < WIN; n++) {
                int q = e + n;
                int loc = q < 24 ? q : 47 - q;
                acc = fmaf(swt[n], sraw[srs][24 + loc], acc);
            }
            obase[(size_t)(TLEN - 12 + e) * NF + srs] = acc;
        }
    }
}

// ---------------------------------------------------------------- launch
extern "C" void kernel_launch(void* const* d_in, const int* in_sizes, int n_in,
                              void* d_out, int out_size) {
    const float* x = (const float*)d_in[0];
    float* out = (float*)d_out;

    size_t smem = BUFSZ * sizeof(float2);   // 34816 B dynamic
    init_kernel<<<16, 256>>>();
    spectral_kernel<<<NB * NF / 2, THR, smem>>>(x, out);
}

// round 13
// speedup vs baseline: 1.9392x; 1.0550x over previous
#include <cuda_runtime.h>

#define NB    32
#define TLEN  4096
#define NF    128
#define NFFT  4096
#define KTOP  16
#define WIN   25
#define HALF  12
#define THR   256
#define BUFSZ 4352               // PAD(4095)=4350 -> need 4351, round to 4352
#define PAD(i) ((i) + ((i) >> 4))

typedef unsigned long long u64;

__device__ float2 g_twf[NFFT];                    // e^{-2pi i k / 4096}
__device__ float2 g_H[NFFT/2 + 1];                // Hamming freq response * (1/4096)

__device__ __forceinline__ float2 cmul(float2 a, float2 b) {
    return make_float2(fmaf(a.x, b.x, -a.y * b.y), fmaf(a.x, b.y, a.y * b.x));
}

// ---------------------------------------------------------------- init
__global__ void init_kernel() {
    int k = blockIdx.x * blockDim.x + threadIdx.x;
    if (k < NFFT) {
        double a = -(double)k / 2048.0;   // pi-units of -2k/4096
        g_twf[k] = make_float2((float)cospi(a), (float)sinpi(a));
    }
    if (k <= NFFT/2) {
        float hr = 0.f, hi = 0.f;
        #pragma unroll 1
        for (int n = 0; n < WIN; n++) {
            float w = (0.54f - 0.46f * cospif(2.0f * (float)n / 25.0f)) * (1.0f / 13.5f);
            float s, c;
            sincospif((float)k * (float)(n - HALF) / 2048.0f, &s, &c);
            hr = fmaf(w, c, hr);
            hi = fmaf(w, s, hi);
        }
        // fold the 1/NFFT inverse-FFT normalization into H
        g_H[k] = make_float2(hr * (1.0f / (float)NFFT), hi * (1.0f / (float)NFFT));
    }
}

// ---------------------------------------------------------------- 4-pt DFT in place
template<bool FWD>
__device__ __forceinline__ void dft4(float2& x0, float2& x1, float2& x2, float2& x3) {
    float2 apc = make_float2(x0.x + x2.x, x0.y + x2.y);
    float2 amc = make_float2(x0.x - x2.x, x0.y - x2.y);
    float2 bpd = make_float2(x1.x + x3.x, x1.y + x3.y);
    float2 bmd = make_float2(x1.x - x3.x, x1.y - x3.y);
    x0 = make_float2(apc.x + bpd.x, apc.y + bpd.y);
    x2 = make_float2(apc.x - bpd.x, apc.y - bpd.y);
    if (FWD) {
        x1 = make_float2(amc.x + bmd.y, amc.y - bmd.x);
        x3 = make_float2(amc.x - bmd.y, amc.y + bmd.x);
    } else {
        x1 = make_float2(amc.x - bmd.y, amc.y + bmd.x);
        x3 = make_float2(amc.x + bmd.y, amc.y - bmd.x);
    }
}

template<bool FWD>
__device__ __forceinline__ float2 twc(float2 a, float cr, float ci) {
    float s = FWD ? ci : -ci;
    return make_float2(fmaf(a.x, cr, -a.y * s), fmaf(a.x, s, a.y * cr));
}

#define C16 0.9238795325112867f
#define S16 0.3826834323650898f
#define RQ2 0.7071067811865476f

// 16-pt DFT in registers; X[q] ends at a[PI(q)] where PI(q) = ((q&3)<<2)|(q>>2)
#define PI(q) ((((q) & 3) << 2) | ((q) >> 2))
template<bool FWD>
__device__ __forceinline__ void dft16(float2* a) {
    dft4<FWD>(a[0], a[4], a[8],  a[12]);
    dft4<FWD>(a[1], a[5], a[9],  a[13]);
    dft4<FWD>(a[2], a[6], a[10], a[14]);
    dft4<FWD>(a[3], a[7], a[11], a[15]);
    a[5]  = twc<FWD>(a[5],   C16, -S16);
    a[9]  = twc<FWD>(a[9],   RQ2, -RQ2);
    a[13] = twc<FWD>(a[13],  S16, -C16);
    a[6]  = twc<FWD>(a[6],   RQ2, -RQ2);
    a[10] = twc<FWD>(a[10],  0.f, -1.f);
    a[14] = twc<FWD>(a[14], -RQ2, -RQ2);
    a[7]  = twc<FWD>(a[7],   S16, -C16);
    a[11] = twc<FWD>(a[11], -RQ2, -RQ2);
    a[15] = twc<FWD>(a[15], -C16,  S16);
    dft4<FWD>(a[0],  a[1],  a[2],  a[3]);
    dft4<FWD>(a[4],  a[5],  a[6],  a[7]);
    dft4<FWD>(a[8],  a[9],  a[10], a[11]);
    dft4<FWD>(a[12], a[13], a[14], a[15]);
}

// stride-256 register load from smem (all stages read this pattern)
__device__ __forceinline__ void fft_load(const float2* buf, int i, float2* a) {
    #pragma unroll
    for (int p = 0; p < 16; p++) a[p] = buf[PAD(i + 256 * p)];
}

// twiddle + scatter-store for Stockham stage ST (0,1 twiddled; 2 plain)
template<bool FWD, int ST>
__device__ __forceinline__ void fft_twstore(float2* buf, int i, const float2* a) {
    const int s = 1 << (4 * ST);
    const int jm = i & ~(s - 1);
    const int off = i + 15 * jm;
    if (ST < 2) {
        float2 w1 = g_twf[jm];
        if (!FWD) w1.y = -w1.y;
        float2 w2 = cmul(w1, w1);
        float2 w3 = cmul(w2, w1);
        float2 w4 = cmul(w2, w2);
        float2 w5 = cmul(w4, w1);
        float2 w6 = cmul(w4, w2);
        float2 w7 = cmul(w4, w3);
        float2 w8 = cmul(w4, w4);
        buf[PAD(off)]        = a[0];
        buf[PAD(off + s)]    = cmul(w1, a[4]);
        buf[PAD(off + 2*s)]  = cmul(w2, a[8]);
        buf[PAD(off + 3*s)]  = cmul(w3, a[12]);
        buf[PAD(off + 4*s)]  = cmul(w4, a[1]);
        buf[PAD(off + 5*s)]  = cmul(w5, a[5]);
        buf[PAD(off + 6*s)]  = cmul(w6, a[9]);
        buf[PAD(off + 7*s)]  = cmul(w7, a[13]);
        buf[PAD(off + 8*s)]  = cmul(w8, a[2]);
        buf[PAD(off + 9*s)]  = cmul(cmul(w8, w1), a[6]);
        buf[PAD(off + 10*s)] = cmul(cmul(w8, w2), a[10]);
        buf[PAD(off + 11*s)] = cmul(cmul(w8, w3), a[14]);
        buf[PAD(off + 12*s)] = cmul(cmul(w8, w4), a[3]);
        buf[PAD(off + 13*s)] = cmul(cmul(w8, w5), a[7]);
        buf[PAD(off + 14*s)] = cmul(cmul(w8, w6), a[11]);
        buf[PAD(off + 15*s)] = cmul(cmul(w8, w7), a[15]);
    } else {
        #pragma unroll
        for (int q = 0; q < 16; q++)
            buf[PAD(off + q * s)] = a[PI(q)];
    }
}

// select k[p] from 8 registers (p in 1..7; else 0), branch-free
__device__ __forceinline__ u64 sel8(const u64* k, int p) {
    u64 r = 0;
    r = (p == 1) ? k[1] : r;
    r = (p == 2) ? k[2] : r;
    r = (p == 3) ? k[3] : r;
    r = (p == 4) ? k[4] : r;
    r = (p == 5) ? k[5] : r;
    r = (p == 6) ? k[6] : r;
    r = (p == 7) ? k[7] : r;
    return r;
}

__device__ __forceinline__ u64 warp_max_u64(u64 v) {
    #pragma unroll
    for (int off = 16; off; off >>= 1) {
        u64 o = __shfl_xor_sync(0xffffffffu, v, off);
        if (o > v) v = o;
    }
    return v;
}

// ---------------------------------------------------------------- fused kernel
__global__ void __launch_bounds__(THR, 4) spectral_kernel(const float* __restrict__ x,
                                                          float* __restrict__ out) {
    extern __shared__ float2 buf[];                 // BUFSZ float2
    __shared__ u64    warpTop[2][8][KTOP];          // per-warp sorted top-16, per series
    __shared__ int    sIdx[2][KTOP];
    __shared__ float2 sVal[2][KTOP];
    __shared__ float  sraw[2][48];
    __shared__ float  swt[WIN];

    const int tid  = threadIdx.x;
    const int wid  = tid >> 5;
    const int lane = tid & 31;
    const int P = blockIdx.x;
    const int b = P >> 6;
    const int f = (P & 63) * 2;
    const float* xin   = x   + (size_t)b * TLEN * NF + f;
    float*       obase = out + (size_t)b * TLEN * NF + f;

    if (tid < WIN)
        swt[tid] = (0.54f - 0.46f * cospif(2.0f * (float)tid / 25.0f)) * (1.0f / 13.5f);

    // ================= forward FFT: stage 0 straight from gmem =================
    float2 a[16];
    #pragma unroll
    for (int p = 0; p < 16; p++)
        a[p] = *(const float2*)(xin + (size_t)(tid + 256 * p) * NF);
    dft16<true>(a);
    fft_twstore<true, 0>(buf, tid, a);
    __syncthreads();
    // stage 1
    fft_load(buf, tid, a);
    __syncthreads();
    dft16<true>(a);
    fft_twstore<true, 1>(buf, tid, a);
    __syncthreads();
    // stage 2 (keep regs: thread holds X[tid + 256q] at a[PI(q)])
    fft_load(buf, tid, a);
    __syncthreads();
    dft16<true>(a);
    fft_twstore<true, 2>(buf, tid, a);
    __syncthreads();

    // ---- keys over bins m = tid + 256k: own z from regs, conjugate partner from smem
    // key = mag_bits<<12 | (4095-m): unique; order == lax.top_k (ties -> lower m)
    u64 kA[8], kB[8];
    #pragma unroll
    for (int k = 0; k < 8; k++) {
        int m = tid + k * THR;                      // 0..2047
        float2 z  = a[PI(k)];
        float2 zm = buf[PAD((NFFT - m) & (NFFT - 1))];
        float ar = z.x + zm.x, ai = z.y - zm.y;     // 2*A[m]
        float br = z.y + zm.y, bi = zm.x - z.x;     // 2*B[m]
        float magA = fmaf(ar, ar, ai * ai);
        float magB = fmaf(br, br, bi * bi);
        kA[k] = ((u64)__float_as_uint(magA) << 12) | (unsigned)(4095 - m);
        kB[k] = ((u64)__float_as_uint(magB) << 12) | (unsigned)(4095 - m);
    }

    // ---- per-thread descending sort (19-comparator network)
    #define CSW(i, j) do { \
        if (kA[i] < kA[j]) { u64 _t = kA[i]; kA[i] = kA[j]; kA[j] = _t; } \
        if (kB[i] < kB[j]) { u64 _t = kB[i]; kB[i] = kB[j]; kB[j] = _t; } \
    } while (0)
    CSW(0,1); CSW(2,3); CSW(4,5); CSW(6,7);
    CSW(0,2); CSW(1,3); CSW(4,6); CSW(5,7);
    CSW(1,2); CSW(5,6);
    CSW(0,4); CSW(1,5); CSW(2,6); CSW(3,7);
    CSW(2,4); CSW(3,5);
    CSW(1,2); CSW(3,4); CSW(5,6);
    #undef CSW

    // ---- warp-local top-16 (no barriers)
    {
        u64 cA = kA[0], cB = kB[0];
        int pA = 1, pB = 1;
        #pragma unroll 1
        for (int it = 0; it < KTOP; it++) {
            u64 wA = warp_max_u64(cA);
            u64 wB = warp_max_u64(cB);
            if (cA == wA) {
                warpTop[0][wid][it] = wA;
                cA = sel8(kA, pA); pA++;
            }
            if (cB == wB) {
                warpTop[1][wid][it] = wB;
                cB = sel8(kB, pB); pB++;
            }
        }
    }
    __syncthreads();

    // ---- CTA merge: warp 0 -> series A, warp 1 -> series B; lane 8 = bin-2048 singleton
    if (wid < 2) {
        const int s = wid;
        u64 cand = 0;
        int p = 1;
        if (lane < 8) cand = warpTop[s][lane][0];
        else if (lane == 8) {
            float2 z = buf[PAD(2048)];
            float mag = (s == 0) ? 4.f * z.x * z.x : 4.f * z.y * z.y;
            cand = ((u64)__float_as_uint(mag) << 12) | (unsigned)(4095 - 2048);
        }
        #pragma unroll 1
        for (int it = 0; it < KTOP; it++) {
            u64 win = warp_max_u64(cand);
            if (cand == win) {
                int m = 4095 - (int)(win & 0xFFFu);
                float2 z  = buf[PAD(m)];
                float2 zm = buf[PAD((NFFT - m) & (NFFT - 1))];
                sIdx[s][it] = m;
                sVal[s][it] = (s == 0)
                    ? make_float2(0.5f * (z.x + zm.x), 0.5f * (z.y - zm.y))
                    : make_float2(0.5f * (z.y + zm.y), 0.5f * (zm.x - z.x));
                if (lane < 8) { cand = (p < KTOP) ? warpTop[s][lane][p] : 0; p++; }
                else cand = 0;
            }
        }
    }
    __syncthreads();   // sIdx/sVal complete; spectrum no longer needed

    // zero buffer; low threads compute raw edge values from the kept bins
    #pragma unroll
    for (int u = 0; u < 16; u++)
        buf[PAD(tid + u * THR)] = make_float2(0.f, 0.f);
    if (tid < 96) {
        int srs = tid & 1, pos = tid >> 1;            // pos 0..47
        int t = pos < 24 ? pos : TLEN - 48 + pos;
        float acc = 0.f;
        #pragma unroll
        for (int j = 0; j < KTOP; j++) {
            int m = sIdx[srs][j];
            float2 v = sVal[srs][j];
            float2 tw = g_twf[(m * t) & (NFFT - 1)];  // conj = e^{+2pi i mt/N}
            float coef = (m == 0 || m == 2048) ? 1.f : 2.f;
            acc = fmaf(coef * v.x, tw.x, acc);
            acc = fmaf(coef * v.y, tw.y, acc);
        }
        sraw[srs][pos] = acc * (1.0f / (float)NFFT);
    }
    __syncthreads();

    // scatter filtered bins (H already carries 1/NFFT): series a
    if (tid < KTOP) {
        int m = sIdx[0][tid];
        float2 vf = cmul(sVal[0][tid], g_H[m]);
        buf[PAD(m)] = vf;
        if (m > 0 && m < 2048) buf[PAD(NFFT - m)] = make_float2(vf.x, -vf.y);
    }
    __syncthreads();
    // series b (additive, times i)
    if (tid < KTOP) {
        int m = sIdx[1][tid];
        float2 wf = cmul(sVal[1][tid], g_H[m]);
        float2 c = buf[PAD(m)];
        c.x -= wf.y; c.y += wf.x;
        buf[PAD(m)] = c;
        if (m > 0 && m < 2048) {
            float2 c2 = buf[PAD(NFFT - m)];
            c2.x += wf.y; c2.y += wf.x;
            buf[PAD(NFFT - m)] = c2;
        }
    }
    __syncthreads();

    // ================= inverse FFT: stages 0,1 in smem; stage 2 -> gmem =================
    fft_load(buf, tid, a);
    __syncthreads();
    dft16<false>(a);
    fft_twstore<false, 0>(buf, tid, a);
    __syncthreads();
    fft_load(buf, tid, a);
    __syncthreads();
    dft16<false>(a);
    fft_twstore<false, 1>(buf, tid, a);
    __syncthreads();
    // final stage: thread holds y[tid + 256q] at a[PI(q)]; store direct (already 1/N-scaled)
    fft_load(buf, tid, a);
    dft16<false>(a);
    #pragma unroll
    for (int q = 0; q < 16; q++) {
        int t = tid + 256 * q;
        bool interior = true;
        if (q == 0)  interior = (tid >= HALF);
        if (q == 15) interior = (tid < 256 - HALF);
        if (interior) {
            float2 z = a[PI(q)];
            *(float2*)(obase + (size_t)t * NF) = z;
        }
    }

    // exact edge outputs via flip-padded direct convolution of raw values
    if (tid < 48) {
        int srs = tid & 1, j = tid >> 1;              // j 0..23
        float acc = 0.f;
        if (j < 12) {                                  // left edge, t = j
            #pragma unroll
            for (int n = 0; n < WIN; n++) {
                int q = j + n - HALF;
                q = q < 0 ? -1 - q : q;
                acc = fmaf(swt[n], sraw[srs][q], acc);
            }
            obase[(size_t)j * NF + srs] = acc;
        } else {                                       // right edge, t = T-12+e
            int e = j - 12;
            #pragma unroll
            for (int n = 0; n < WIN; n++) {
                int q = e + n;
                int loc = q < 24 ? q : 47 - q;
                acc = fmaf(swt[n], sraw[srs][24 + loc], acc);
            }
            obase[(size_t)(TLEN - 12 + e) * NF + srs] = acc;
        }
    }
}

// ---------------------------------------------------------------- launch
extern "C" void kernel_launch(void* const* d_in, const int* in_sizes, int n_in,
                              void* d_out, int out_size) {
    const float* x = (const float*)d_in[0];
    float* out = (float*)d_out;

    size_t smem = BUFSZ * sizeof(float2);   // 34816 B dynamic
    init_kernel<<<16, 256>>>();
    spectral_kernel<<<NB * NF / 2, THR, smem>>>(x, out);
}